// round 3
// baseline (speedup 1.0000x reference)
#include <cuda_runtime.h>

// UnPooling (max-unpool 2x2): x [16,128,128,256] f32, pooled [16,64,64,256] f32
// out [16,128,128,256] f32: max(pooled,0) at argmax slot of each 2x2 window, else 0.
//
// NHWC, hardcoded: N=16, H=128, W=128, C=256, Hp=64, Wp=64.
// 256-bit vectorization over channels: 8 floats (two float4) per thread,
// 32-byte aligned so ptxas can emit LDG.E.256 / STG.E.256 on sm_103a.
// In f8 units: C/8 = 32 per pixel; x row stride = 128*32 = 4096, col stride = 32.

struct __align__(32) f8 {
    float4 lo;
    float4 hi;
};

__global__ __launch_bounds__(256) void unpool_kernel(const f8* __restrict__ x,
                                                     const f8* __restrict__ pooled,
                                                     f8* __restrict__ out,
                                                     int total)
{
    int tid = blockIdx.x * blockDim.x + threadIdx.x;
    if (tid >= total) return;

    // tid linear over pooled in f8 units: ((n*Hp+hp)*Wp+wp)*32 + c8
    int c8 = tid & 31;          // C/8 = 32
    int wp = (tid >> 5) & 63;   // Wp = 64
    int hp = (tid >> 11) & 63;  // Hp = 64
    int n  = tid >> 17;

    // base f8 index into x/out at (n, 2*hp, 2*wp, c8)
    int b = ((n * 128 + 2 * hp) * 128 + 2 * wp) * 32 + c8;

    f8 v00 = x[b];
    f8 v01 = x[b + 32];      // (dh=0, dw=1)
    f8 v10 = x[b + 4096];    // (dh=1, dw=0)
    f8 v11 = x[b + 4128];    // (dh=1, dw=1)
    f8 p   = pooled[tid];

    f8 o00, o01, o10, o11;

    // Row-major (dh,dw) order, first-max tie-break => strict '>' for later slots.
#define UNPOOL_COMP(H, F)                                             \
    {                                                                 \
        float t0 = v00.H.F, t1 = v01.H.F, t2 = v10.H.F, t3 = v11.H.F; \
        int   idx = 0;                                                \
        float best = t0;                                              \
        if (t1 > best) { best = t1; idx = 1; }                        \
        if (t2 > best) { best = t2; idx = 2; }                        \
        if (t3 > best) { best = t3; idx = 3; }                        \
        float pv = fmaxf(p.H.F, 0.0f);                                \
        o00.H.F = (idx == 0) ? pv : 0.0f;                             \
        o01.H.F = (idx == 1) ? pv : 0.0f;                             \
        o10.H.F = (idx == 2) ? pv : 0.0f;                             \
        o11.H.F = (idx == 3) ? pv : 0.0f;                             \
    }

    UNPOOL_COMP(lo, x)
    UNPOOL_COMP(lo, y)
    UNPOOL_COMP(lo, z)
    UNPOOL_COMP(lo, w)
    UNPOOL_COMP(hi, x)
    UNPOOL_COMP(hi, y)
    UNPOOL_COMP(hi, z)
    UNPOOL_COMP(hi, w)
#undef UNPOOL_COMP

    out[b]        = o00;
    out[b + 32]   = o01;
    out[b + 4096] = o10;
    out[b + 4128] = o11;
}

extern "C" void kernel_launch(void* const* d_in, const int* in_sizes, int n_in,
                              void* d_out, int out_size)
{
    const f8* x      = (const f8*)d_in[0];
    const f8* pooled = (const f8*)d_in[1];
    f8*       out    = (f8*)d_out;

    const int total = 16 * 64 * 64 * 32;   // pooled f8 count = 2,097,152
    const int threads = 256;
    const int blocks  = (total + threads - 1) / threads;
    unpool_kernel<<<blocks, threads>>>(x, pooled, out, total);
}

// round 4
// speedup vs baseline: 1.0099x; 1.0099x over previous
#include <cuda_runtime.h>

// UnPooling (max-unpool 2x2): x [16,128,128,256] f32, pooled [16,64,64,256] f32
// out [16,128,128,256] f32: max(pooled,0) at argmax slot of each 2x2 window, else 0.
//
// NHWC, hardcoded: N=16, H=128, W=128, C=256, Hp=64, Wp=64.
// Proven-best memory shape (R1): 128-bit accesses, 28 regs, high occupancy.
// CV = C/4 = 64 float4 per pixel; x row stride 8192, col stride 64 (float4 units).

__global__ __launch_bounds__(512) void unpool_kernel(const float4* __restrict__ x,
                                                     const float4* __restrict__ pooled,
                                                     float4* __restrict__ out,
                                                     int total)
{
    int tid = blockIdx.x * blockDim.x + threadIdx.x;
    if (tid >= total) return;

    // tid linear over pooled in float4 units: ((n*Hp+hp)*Wp+wp)*CV + cv
    int cv = tid & 63;          // CV = 64
    int wp = (tid >> 6) & 63;   // Wp = 64
    int hp = (tid >> 12) & 63;  // Hp = 64
    int n  = tid >> 18;

    // base float4 index into x/out at (n, 2*hp, 2*wp, cv)
    int b = ((n * 128 + 2 * hp) * 128 + 2 * wp) * 64 + cv;

    float4 v00 = x[b];
    float4 v01 = x[b + 64];      // (dh=0, dw=1)
    float4 v10 = x[b + 8192];    // (dh=1, dw=0)
    float4 v11 = x[b + 8256];    // (dh=1, dw=1)
    float4 p   = pooled[tid];

    float4 o00, o01, o10, o11;

    // Row-major (dh,dw) order, first-max tie-break => strict '>' for later slots.
#define UNPOOL_COMP(F)                                                \
    {                                                                 \
        float t0 = v00.F, t1 = v01.F, t2 = v10.F, t3 = v11.F;         \
        int   idx = 0;                                                \
        float best = t0;                                              \
        if (t1 > best) { best = t1; idx = 1; }                        \
        if (t2 > best) { best = t2; idx = 2; }                        \
        if (t3 > best) { best = t3; idx = 3; }                        \
        float pv = fmaxf(p.F, 0.0f);                                  \
        o00.F = (idx == 0) ? pv : 0.0f;                               \
        o01.F = (idx == 1) ? pv : 0.0f;                               \
        o10.F = (idx == 2) ? pv : 0.0f;                               \
        o11.F = (idx == 3) ? pv : 0.0f;                               \
    }

    UNPOOL_COMP(x)
    UNPOOL_COMP(y)
    UNPOOL_COMP(z)
    UNPOOL_COMP(w)
#undef UNPOOL_COMP

    out[b]        = o00;
    out[b + 64]   = o01;
    out[b + 8192] = o10;
    out[b + 8256] = o11;
}

extern "C" void kernel_launch(void* const* d_in, const int* in_sizes, int n_in,
                              void* d_out, int out_size)
{
    const float4* x      = (const float4*)d_in[0];
    const float4* pooled = (const float4*)d_in[1];
    float4*       out    = (float4*)d_out;

    const int total = 16 * 64 * 64 * 64;   // pooled float4 count = 4,194,304
    const int threads = 512;
    const int blocks  = (total + threads - 1) / threads;
    unpool_kernel<<<blocks, threads>>>(x, pooled, out, total);
}